// round 2
// baseline (speedup 1.0000x reference)
#include <cuda_runtime.h>
#include <cuda_bf16.h>
#include <math.h>

#define CDIM   192
#define KVDIM  384
#define HEADS  6
#define CPH    32
#define WIDTH  160
#define HW     25600          // 160*160
#define BATCH  8
#define NSPLIT 16

// ---------------- scratch (device globals; no allocation) ----------------
__device__ float g_q   [(size_t)BATCH * CDIM  * HW];   // q after 1x1
__device__ float g_kv  [(size_t)BATCH * KVDIM * HW];   // kv after 1x1
__device__ float g_qd  [(size_t)BATCH * CDIM  * HW];   // q after dw3x3
__device__ float g_kvd [(size_t)BATCH * KVDIM * HW];   // k|v after dw3x3
__device__ float g_S   [BATCH * HEADS * CPH * CPH];    // raw gram
__device__ float g_NQ  [BATCH * HEADS * CPH];          // sum q^2
__device__ float g_NK  [BATCH * HEADS * CPH];          // sum k^2
__device__ float g_A   [BATCH * HEADS * CPH * CPH];    // softmax(attn)
__device__ float g_M   [(size_t)BATCH * CDIM * CDIM];  // W_out @ blockdiag(A)

// ---------------- 1x1 conv == per-batch GEMM: Y[b,o,n] = sum_c W[o,c] X[b,c,n]
// BM=64 (o), BN=64 (n), BK=16 (c), 256 threads, 4x4 microtile.
__global__ __launch_bounds__(256) void gemm1x1(
    const float* __restrict__ W, const float* __restrict__ X, float* __restrict__ Y,
    int O, long wBatchStride, long xBatchStride)
{
    __shared__ float Ws[16][64];
    __shared__ float Xs[16][64];
    const int tid = threadIdx.x;
    const int n0 = blockIdx.x * 64;
    const int o0 = blockIdx.y * 64;
    const int b  = blockIdx.z;
    const float* Wb = W + (size_t)b * wBatchStride;
    const float* Xb = X + (size_t)b * xBatchStride;
    const int tm = tid >> 4, tn = tid & 15;

    float acc[4][4] = {};
    for (int c0 = 0; c0 < CDIM; c0 += 16) {
        #pragma unroll
        for (int i = 0; i < 4; i++) {
            int e = tid + i * 256;           // 1024 W elems
            int m = e >> 4, k = e & 15;
            Ws[k][m] = Wb[(size_t)(o0 + m) * CDIM + c0 + k];
        }
        #pragma unroll
        for (int i = 0; i < 4; i++) {
            int e = tid + i * 256;           // 1024 X elems
            int k = e >> 6, n = e & 63;
            Xs[k][n] = Xb[(size_t)(c0 + k) * HW + n0 + n];
        }
        __syncthreads();
        #pragma unroll
        for (int k = 0; k < 16; k++) {
            float4 a  = *(const float4*)&Ws[k][tm * 4];
            float4 bx = *(const float4*)&Xs[k][tn * 4];
            float av[4] = {a.x, a.y, a.z, a.w};
            float bv[4] = {bx.x, bx.y, bx.z, bx.w};
            #pragma unroll
            for (int i = 0; i < 4; i++)
                #pragma unroll
                for (int j = 0; j < 4; j++)
                    acc[i][j] += av[i] * bv[j];
        }
        __syncthreads();
    }
    #pragma unroll
    for (int i = 0; i < 4; i++) {
        float4 v = make_float4(acc[i][0], acc[i][1], acc[i][2], acc[i][3]);
        *(float4*)&Y[((size_t)b * O + o0 + tm * 4 + i) * HW + n0 + tn * 4] = v;
    }
}

// ---------------- depthwise 3x3, pad 1 (cross-correlation, zero fill) ------
__global__ __launch_bounds__(256) void dwconv3x3(
    const float* __restrict__ X, const float* __restrict__ Wd,
    float* __restrict__ Y, int C)
{
    const int b = blockIdx.z, c = blockIdx.y;
    const int idx = blockIdx.x * 256 + threadIdx.x;     // 0..HW-1
    const int h = idx / WIDTH, w = idx % WIDTH;
    const float* xp = X + ((size_t)b * C + c) * HW;
    const float* wp = Wd + c * 9;
    float acc = 0.f;
    #pragma unroll
    for (int i = 0; i < 3; i++) {
        int hh = h + i - 1;
        if (hh < 0 || hh >= WIDTH) continue;
        #pragma unroll
        for (int j = 0; j < 3; j++) {
            int ww = w + j - 1;
            if (ww < 0 || ww >= WIDTH) continue;
            acc += wp[i * 3 + j] * xp[hh * WIDTH + ww];
        }
    }
    Y[((size_t)b * C + c) * HW + idx] = acc;
}

// ---------------- zero the gram accumulators -------------------------------
__global__ void zero_acc() {
    int i = blockIdx.x * 256 + threadIdx.x;
    const int nS = BATCH * HEADS * CPH * CPH;
    const int nN = BATCH * HEADS * CPH;
    if (i < nS) g_S[i] = 0.f;
    if (i < nN) { g_NQ[i] = 0.f; g_NK[i] = 0.f; }
}

// ---------------- Gram: S[b,h,c,d] = sum_n q[c,n] k[d,n]; plus sum q^2, k^2
// grid (NSPLIT, HEADS, BATCH); 256 threads = 16x16, 2x2 microtile.
__global__ __launch_bounds__(256) void gram(
    const float* __restrict__ Q, const float* __restrict__ K)
{
    __shared__ float qs[32][33];
    __shared__ float ks[32][33];
    const int b = blockIdx.z, hh = blockIdx.y, split = blockIdx.x;
    const int tid = threadIdx.x;
    const float* qb = Q + ((size_t)b * CDIM  + hh * CPH) * HW;
    const float* kb = K + ((size_t)b * KVDIM + hh * CPH) * HW;   // k = first half of kvd
    const int chunk = HW / NSPLIT;
    const int nbeg = split * chunk;
    const int ty = tid >> 4, tx = tid & 15;
    const int lc = tid >> 3;          // 0..31 row for staging
    const int lj = (tid & 7) * 4;     // 0..28 col group

    float acc00 = 0, acc01 = 0, acc10 = 0, acc11 = 0;
    float aq0 = 0, aq1 = 0, ak0 = 0, ak1 = 0;

    for (int n0 = nbeg; n0 < nbeg + chunk; n0 += 32) {
        float4 vq = *(const float4*)&qb[(size_t)lc * HW + n0 + lj];
        float4 vk = *(const float4*)&kb[(size_t)lc * HW + n0 + lj];
        qs[lc][lj] = vq.x; qs[lc][lj+1] = vq.y; qs[lc][lj+2] = vq.z; qs[lc][lj+3] = vq.w;
        ks[lc][lj] = vk.x; ks[lc][lj+1] = vk.y; ks[lc][lj+2] = vk.z; ks[lc][lj+3] = vk.w;
        __syncthreads();
        #pragma unroll
        for (int t = 0; t < 32; t++) {
            float q0 = qs[ty*2][t],  q1 = qs[ty*2+1][t];
            float k0 = ks[tx*2][t],  k1 = ks[tx*2+1][t];
            acc00 += q0*k0; acc01 += q0*k1; acc10 += q1*k0; acc11 += q1*k1;
            if (tx == 0) { aq0 += q0*q0; aq1 += q1*q1; }
            if (ty == 0) { ak0 += k0*k0; ak1 += k1*k1; }
        }
        __syncthreads();
    }
    float* Sb = g_S + (size_t)(b * HEADS + hh) * CPH * CPH;
    atomicAdd(&Sb[(ty*2    ) * CPH + tx*2    ], acc00);
    atomicAdd(&Sb[(ty*2    ) * CPH + tx*2 + 1], acc01);
    atomicAdd(&Sb[(ty*2 + 1) * CPH + tx*2    ], acc10);
    atomicAdd(&Sb[(ty*2 + 1) * CPH + tx*2 + 1], acc11);
    if (tx == 0) {
        atomicAdd(&g_NQ[(b * HEADS + hh) * CPH + ty*2    ], aq0);
        atomicAdd(&g_NQ[(b * HEADS + hh) * CPH + ty*2 + 1], aq1);
    }
    if (ty == 0) {
        atomicAdd(&g_NK[(b * HEADS + hh) * CPH + tx*2    ], ak0);
        atomicAdd(&g_NK[(b * HEADS + hh) * CPH + tx*2 + 1], ak1);
    }
}

// ---------------- softmax over d with L2-norm scaling + temperature --------
__global__ void softmax_attn(const float* __restrict__ temp) {
    const int bh = blockIdx.x;          // b*HEADS + h
    const int h  = bh % HEADS;
    const int d  = threadIdx.x;         // 32 lanes
    const float t = temp[h];
    float nk = fmaxf(sqrtf(g_NK[bh * CPH + d]), 1e-12f);
    for (int c = 0; c < CPH; c++) {
        float nq = fmaxf(sqrtf(g_NQ[bh * CPH + c]), 1e-12f);
        float v = g_S[bh * CPH * CPH + c * CPH + d] / (nq * nk) * t;
        float m = v;
        #pragma unroll
        for (int o = 16; o; o >>= 1) m = fmaxf(m, __shfl_xor_sync(~0u, m, o));
        float e = __expf(v - m);
        float s = e;
        #pragma unroll
        for (int o = 16; o; o >>= 1) s += __shfl_xor_sync(~0u, s, o);
        g_A[bh * CPH * CPH + c * CPH + d] = e / s;
    }
}

// ---------------- fold: M[b,o,g] = sum_c Wout[o, h*32+c] * A[b,h,c,d], g=h*32+d
__global__ __launch_bounds__(256) void foldM(const float* __restrict__ Wout) {
    const int b = blockIdx.y;
    const int idx = blockIdx.x * 256 + threadIdx.x;     // 0..192*192-1
    const int o = idx / CDIM, g = idx % CDIM;
    const int h = g / CPH, d = g % CPH;
    const float* Ab = g_A + (size_t)(b * HEADS + h) * CPH * CPH;
    float acc = 0.f;
    #pragma unroll
    for (int c = 0; c < CPH; c++)
        acc += Wout[o * CDIM + h * CPH + c] * Ab[c * CPH + d];
    g_M[(size_t)b * CDIM * CDIM + idx] = acc;
}

// ---------------- launch --------------------------------------------------
extern "C" void kernel_launch(void* const* d_in, const int* in_sizes, int n_in,
                              void* d_out, int out_size)
{
    const float* x_q   = (const float*)d_in[0];
    const float* x_kv  = (const float*)d_in[1];
    const float* w_q   = (const float*)d_in[2];
    const float* w_kv  = (const float*)d_in[3];
    const float* w_qdw = (const float*)d_in[4];
    const float* w_kvdw= (const float*)d_in[5];
    const float* w_out = (const float*)d_in[6];
    const float* temp  = (const float*)d_in[7];
    float* out = (float*)d_out;

    float *bq, *bkv, *bqd, *bkvd, *bM;
    cudaGetSymbolAddress((void**)&bq,   g_q);
    cudaGetSymbolAddress((void**)&bkv,  g_kv);
    cudaGetSymbolAddress((void**)&bqd,  g_qd);
    cudaGetSymbolAddress((void**)&bkvd, g_kvd);
    cudaGetSymbolAddress((void**)&bM,   g_M);

    // 1) q = W_q @ x_q  (per batch 192x25600x192)
    gemm1x1<<<dim3(HW/64, CDIM/64, BATCH), 256>>>(w_q, x_q, bq, CDIM, 0, (long)CDIM * HW);
    // 2) kv = W_kv @ x_kv (384 outputs)
    gemm1x1<<<dim3(HW/64, KVDIM/64, BATCH), 256>>>(w_kv, x_kv, bkv, KVDIM, 0, (long)CDIM * HW);
    // 3) depthwise 3x3
    dwconv3x3<<<dim3(HW/256, CDIM,  BATCH), 256>>>(bq,  w_qdw,  bqd,  CDIM);
    dwconv3x3<<<dim3(HW/256, KVDIM, BATCH), 256>>>(bkv, w_kvdw, bkvd, KVDIM);
    // 4) zero gram accumulators
    zero_acc<<<(BATCH*HEADS*CPH*CPH + 255)/256, 256>>>();
    // 5) gram + norms (k = first DIM channels of kvd)
    gram<<<dim3(NSPLIT, HEADS, BATCH), 256>>>(bqd, bkvd);
    // 6) softmax with normalization + temperature
    softmax_attn<<<BATCH * HEADS, 32>>>(temp);
    // 7) fold W_out with attention
    foldM<<<dim3(CDIM*CDIM/256, BATCH), 256>>>(w_out);
    // 8) out = M_b @ v  (v = second DIM channels of kvd)
    gemm1x1<<<dim3(HW/64, CDIM/64, BATCH), 256>>>(
        bM, bkvd + (size_t)CDIM * HW, out, CDIM,
        (long)CDIM * CDIM, (long)KVDIM * HW);
}

// round 8
// speedup vs baseline: 1.4069x; 1.4069x over previous
#include <cuda_runtime.h>
#include <cuda_bf16.h>
#include <math.h>

#define CDIM   192
#define KVDIM  384
#define HEADS  6
#define CPH    32
#define WIDTH  160
#define HW     25600          // 160*160
#define BATCH  8
#define NSPLIT 16

// ---------------- scratch (device globals; no allocation) ----------------
__device__ float g_q   [(size_t)BATCH * CDIM  * HW];   // q after 1x1
__device__ float g_kv  [(size_t)BATCH * KVDIM * HW];   // kv after 1x1
__device__ float g_qd  [(size_t)BATCH * CDIM  * HW];   // q after dw3x3
__device__ float g_kvd [(size_t)BATCH * KVDIM * HW];   // k|v after dw3x3
__device__ float g_S   [BATCH * HEADS * CPH * CPH];    // raw gram
__device__ float g_NQ  [BATCH * HEADS * CPH];          // sum q^2
__device__ float g_NK  [BATCH * HEADS * CPH];          // sum k^2
__device__ float g_A   [BATCH * HEADS * CPH * CPH];    // softmax(attn)
__device__ float g_M   [(size_t)BATCH * CDIM * CDIM];  // W_out @ blockdiag(A)

// ---------------- 1x1 conv == per-batch GEMM: Y[b,o,n] = sum_c W[o,c] X[b,c,n]
// BM=64 (o), BN=128 (n), BK=16 (c), 128 threads, 8x8 microtile,
// double-buffered smem with register prefetch. K is always 192.
__global__ __launch_bounds__(128) void gemm_v2(
    const float* __restrict__ W, const float* __restrict__ X, float* __restrict__ Y,
    int O, long wBatchStride, long xBatchStride)
{
    __shared__ float As[2][16][68];    // [k][m], padded
    __shared__ float Xs[2][16][128];   // [k][n]
    const int tid = threadIdx.x;
    const int n0 = blockIdx.x * 128;
    const int o0 = blockIdx.y * 64;
    const int b  = blockIdx.z;
    const float* Wb = W + (size_t)b * wBatchStride + (size_t)o0 * CDIM;
    const float* Xb = X + (size_t)b * xBatchStride + n0;
    const int tm = tid >> 4;        // 0..7  -> m micro-row * 8
    const int tn = tid & 15;        // 0..15 -> n micro-col * 8

    float4 aReg[2], xReg[4];

    // ---- prologue: load k-block 0 into regs, store to smem buf 0 ----
    #pragma unroll
    for (int i = 0; i < 2; i++) {
        int f4 = tid * 2 + i;                 // 0..255
        int row = f4 >> 2, kc = (f4 & 3) * 4;
        aReg[i] = *(const float4*)&Wb[(size_t)row * CDIM + kc];
    }
    #pragma unroll
    for (int i = 0; i < 4; i++) {
        int f4 = tid + i * 128;               // 0..511
        int k = f4 >> 5, nn = (f4 & 31) * 4;
        xReg[i] = *(const float4*)&Xb[(size_t)k * HW + nn];
    }
    #pragma unroll
    for (int i = 0; i < 2; i++) {
        int f4 = tid * 2 + i;
        int row = f4 >> 2, kc = (f4 & 3) * 4;
        As[0][kc + 0][row] = aReg[i].x;
        As[0][kc + 1][row] = aReg[i].y;
        As[0][kc + 2][row] = aReg[i].z;
        As[0][kc + 3][row] = aReg[i].w;
    }
    #pragma unroll
    for (int i = 0; i < 4; i++) {
        int f4 = tid + i * 128;
        int k = f4 >> 5, nn = (f4 & 31) * 4;
        *(float4*)&Xs[0][k][nn] = xReg[i];
    }
    __syncthreads();

    float acc[8][8] = {};
    int buf = 0;

    #pragma unroll 1
    for (int it = 0; it < 12; it++) {         // 12 * BK16 = K192
        // prefetch next k-block into registers (latency hidden by compute)
        if (it < 11) {
            int c1 = (it + 1) * 16;
            #pragma unroll
            for (int i = 0; i < 2; i++) {
                int f4 = tid * 2 + i;
                int row = f4 >> 2, kc = (f4 & 3) * 4;
                aReg[i] = *(const float4*)&Wb[(size_t)row * CDIM + c1 + kc];
            }
            #pragma unroll
            for (int i = 0; i < 4; i++) {
                int f4 = tid + i * 128;
                int k = f4 >> 5, nn = (f4 & 31) * 4;
                xReg[i] = *(const float4*)&Xb[(size_t)(c1 + k) * HW + nn];
            }
        }
        // compute on current buffer: 16 k-steps x 64 FMA
        #pragma unroll
        for (int k = 0; k < 16; k++) {
            float4 a0 = *(const float4*)&As[buf][k][tm * 8];
            float4 a1 = *(const float4*)&As[buf][k][tm * 8 + 4];
            float4 b0 = *(const float4*)&Xs[buf][k][tn * 8];
            float4 b1 = *(const float4*)&Xs[buf][k][tn * 8 + 4];
            float av[8] = {a0.x, a0.y, a0.z, a0.w, a1.x, a1.y, a1.z, a1.w};
            float bv[8] = {b0.x, b0.y, b0.z, b0.w, b1.x, b1.y, b1.z, b1.w};
            #pragma unroll
            for (int i = 0; i < 8; i++)
                #pragma unroll
                for (int j = 0; j < 8; j++)
                    acc[i][j] += av[i] * bv[j];
        }
        // stage prefetched regs into the other buffer
        if (it < 11) {
            int nb = buf ^ 1;
            #pragma unroll
            for (int i = 0; i < 2; i++) {
                int f4 = tid * 2 + i;
                int row = f4 >> 2, kc = (f4 & 3) * 4;
                As[nb][kc + 0][row] = aReg[i].x;
                As[nb][kc + 1][row] = aReg[i].y;
                As[nb][kc + 2][row] = aReg[i].z;
                As[nb][kc + 3][row] = aReg[i].w;
            }
            #pragma unroll
            for (int i = 0; i < 4; i++) {
                int f4 = tid + i * 128;
                int k = f4 >> 5, nn = (f4 & 31) * 4;
                *(float4*)&Xs[nb][k][nn] = xReg[i];
            }
        }
        __syncthreads();
        buf ^= 1;
    }

    // ---- epilogue: 8x8 per thread, two float4 stores per row ----
    #pragma unroll
    for (int i = 0; i < 8; i++) {
        size_t base = ((size_t)b * O + o0 + tm * 8 + i) * HW + n0 + tn * 8;
        *(float4*)&Y[base]     = make_float4(acc[i][0], acc[i][1], acc[i][2], acc[i][3]);
        *(float4*)&Y[base + 4] = make_float4(acc[i][4], acc[i][5], acc[i][6], acc[i][7]);
    }
}

// ---------------- depthwise 3x3, pad 1 (cross-correlation, zero fill) ------
__global__ __launch_bounds__(256) void dwconv3x3(
    const float* __restrict__ X, const float* __restrict__ Wd,
    float* __restrict__ Y, int C)
{
    const int b = blockIdx.z, c = blockIdx.y;
    const int idx = blockIdx.x * 256 + threadIdx.x;     // 0..HW-1
    const int h = idx / WIDTH, w = idx % WIDTH;
    const float* xp = X + ((size_t)b * C + c) * HW;
    const float* wp = Wd + c * 9;
    float acc = 0.f;
    #pragma unroll
    for (int i = 0; i < 3; i++) {
        int hh = h + i - 1;
        if (hh < 0 || hh >= WIDTH) continue;
        #pragma unroll
        for (int j = 0; j < 3; j++) {
            int ww = w + j - 1;
            if (ww < 0 || ww >= WIDTH) continue;
            acc += wp[i * 3 + j] * xp[hh * WIDTH + ww];
        }
    }
    Y[((size_t)b * C + c) * HW + idx] = acc;
}

// ---------------- zero the gram accumulators -------------------------------
__global__ void zero_acc() {
    int i = blockIdx.x * 256 + threadIdx.x;
    const int nS = BATCH * HEADS * CPH * CPH;
    const int nN = BATCH * HEADS * CPH;
    if (i < nS) g_S[i] = 0.f;
    if (i < nN) { g_NQ[i] = 0.f; g_NK[i] = 0.f; }
}

// ---------------- Gram: S[b,h,c,d] = sum_n q[c,n] k[d,n]; plus sum q^2, k^2
// grid (NSPLIT, HEADS, BATCH); 256 threads = 16x16, 2x2 microtile.
__global__ __launch_bounds__(256) void gram(
    const float* __restrict__ Q, const float* __restrict__ K)
{
    __shared__ float qs[32][33];
    __shared__ float ks[32][33];
    const int b = blockIdx.z, hh = blockIdx.y, split = blockIdx.x;
    const int tid = threadIdx.x;
    const float* qb = Q + ((size_t)b * CDIM  + hh * CPH) * HW;
    const float* kb = K + ((size_t)b * KVDIM + hh * CPH) * HW;   // k = first half of kvd
    const int chunk = HW / NSPLIT;
    const int nbeg = split * chunk;
    const int ty = tid >> 4, tx = tid & 15;
    const int lc = tid >> 3;          // 0..31 row for staging
    const int lj = (tid & 7) * 4;     // 0..28 col group

    float acc00 = 0, acc01 = 0, acc10 = 0, acc11 = 0;
    float aq0 = 0, aq1 = 0, ak0 = 0, ak1 = 0;

    for (int n0 = nbeg; n0 < nbeg + chunk; n0 += 32) {
        float4 vq = *(const float4*)&qb[(size_t)lc * HW + n0 + lj];
        float4 vk = *(const float4*)&kb[(size_t)lc * HW + n0 + lj];
        qs[lc][lj] = vq.x; qs[lc][lj+1] = vq.y; qs[lc][lj+2] = vq.z; qs[lc][lj+3] = vq.w;
        ks[lc][lj] = vk.x; ks[lc][lj+1] = vk.y; ks[lc][lj+2] = vk.z; ks[lc][lj+3] = vk.w;
        __syncthreads();
        #pragma unroll
        for (int t = 0; t < 32; t++) {
            float q0 = qs[ty*2][t],  q1 = qs[ty*2+1][t];
            float k0 = ks[tx*2][t],  k1 = ks[tx*2+1][t];
            acc00 += q0*k0; acc01 += q0*k1; acc10 += q1*k0; acc11 += q1*k1;
            if (tx == 0) { aq0 += q0*q0; aq1 += q1*q1; }
            if (ty == 0) { ak0 += k0*k0; ak1 += k1*k1; }
        }
        __syncthreads();
    }
    float* Sb = g_S + (size_t)(b * HEADS + hh) * CPH * CPH;
    atomicAdd(&Sb[(ty*2    ) * CPH + tx*2    ], acc00);
    atomicAdd(&Sb[(ty*2    ) * CPH + tx*2 + 1], acc01);
    atomicAdd(&Sb[(ty*2 + 1) * CPH + tx*2    ], acc10);
    atomicAdd(&Sb[(ty*2 + 1) * CPH + tx*2 + 1], acc11);
    if (tx == 0) {
        atomicAdd(&g_NQ[(b * HEADS + hh) * CPH + ty*2    ], aq0);
        atomicAdd(&g_NQ[(b * HEADS + hh) * CPH + ty*2 + 1], aq1);
    }
    if (ty == 0) {
        atomicAdd(&g_NK[(b * HEADS + hh) * CPH + tx*2    ], ak0);
        atomicAdd(&g_NK[(b * HEADS + hh) * CPH + tx*2 + 1], ak1);
    }
}

// ---------------- softmax over d with L2-norm scaling + temperature --------
__global__ void softmax_attn(const float* __restrict__ temp) {
    const int bh = blockIdx.x;          // b*HEADS + h
    const int h  = bh % HEADS;
    const int d  = threadIdx.x;         // 32 lanes
    const float t = temp[h];
    float nk = fmaxf(sqrtf(g_NK[bh * CPH + d]), 1e-12f);
    for (int c = 0; c < CPH; c++) {
        float nq = fmaxf(sqrtf(g_NQ[bh * CPH + c]), 1e-12f);
        float v = g_S[bh * CPH * CPH + c * CPH + d] / (nq * nk) * t;
        float m = v;
        #pragma unroll
        for (int o = 16; o; o >>= 1) m = fmaxf(m, __shfl_xor_sync(~0u, m, o));
        float e = __expf(v - m);
        float s = e;
        #pragma unroll
        for (int o = 16; o; o >>= 1) s += __shfl_xor_sync(~0u, s, o);
        g_A[bh * CPH * CPH + c * CPH + d] = e / s;
    }
}

// ---------------- fold: M[b,o,g] = sum_c Wout[o, h*32+c] * A[b,h,c,d], g=h*32+d
__global__ __launch_bounds__(256) void foldM(const float* __restrict__ Wout) {
    const int b = blockIdx.y;
    const int idx = blockIdx.x * 256 + threadIdx.x;     // 0..192*192-1
    const int o = idx / CDIM, g = idx % CDIM;
    const int h = g / CPH, d = g % CPH;
    const float* Ab = g_A + (size_t)(b * HEADS + h) * CPH * CPH;
    float acc = 0.f;
    #pragma unroll
    for (int c = 0; c < CPH; c++)
        acc += Wout[o * CDIM + h * CPH + c] * Ab[c * CPH + d];
    g_M[(size_t)b * CDIM * CDIM + idx] = acc;
}

// ---------------- launch --------------------------------------------------
extern "C" void kernel_launch(void* const* d_in, const int* in_sizes, int n_in,
                              void* d_out, int out_size)
{
    const float* x_q   = (const float*)d_in[0];
    const float* x_kv  = (const float*)d_in[1];
    const float* w_q   = (const float*)d_in[2];
    const float* w_kv  = (const float*)d_in[3];
    const float* w_qdw = (const float*)d_in[4];
    const float* w_kvdw= (const float*)d_in[5];
    const float* w_out = (const float*)d_in[6];
    const float* temp  = (const float*)d_in[7];
    float* out = (float*)d_out;

    float *bq, *bkv, *bqd, *bkvd, *bM;
    cudaGetSymbolAddress((void**)&bq,   g_q);
    cudaGetSymbolAddress((void**)&bkv,  g_kv);
    cudaGetSymbolAddress((void**)&bqd,  g_qd);
    cudaGetSymbolAddress((void**)&bkvd, g_kvd);
    cudaGetSymbolAddress((void**)&bM,   g_M);

    // 1) q = W_q @ x_q  (per batch 192x25600x192)
    gemm_v2<<<dim3(HW/128, CDIM/64, BATCH), 128>>>(w_q, x_q, bq, CDIM, 0, (long)CDIM * HW);
    // 2) kv = W_kv @ x_kv (384 outputs)
    gemm_v2<<<dim3(HW/128, KVDIM/64, BATCH), 128>>>(w_kv, x_kv, bkv, KVDIM, 0, (long)CDIM * HW);
    // 3) depthwise 3x3
    dwconv3x3<<<dim3(HW/256, CDIM,  BATCH), 256>>>(bq,  w_qdw,  bqd,  CDIM);
    dwconv3x3<<<dim3(HW/256, KVDIM, BATCH), 256>>>(bkv, w_kvdw, bkvd, KVDIM);
    // 4) zero gram accumulators
    zero_acc<<<(BATCH*HEADS*CPH*CPH + 255)/256, 256>>>();
    // 5) gram + norms (k = first DIM channels of kvd)
    gram<<<dim3(NSPLIT, HEADS, BATCH), 256>>>(bqd, bkvd);
    // 6) softmax with normalization + temperature
    softmax_attn<<<BATCH * HEADS, 32>>>(temp);
    // 7) fold W_out with attention
    foldM<<<dim3(CDIM*CDIM/256, BATCH), 256>>>(w_out);
    // 8) out = M_b @ v  (v = second DIM channels of kvd)
    gemm_v2<<<dim3(HW/128, CDIM/64, BATCH), 128>>>(
        bM, bkvd + (size_t)CDIM * HW, out, CDIM,
        (long)CDIM * CDIM, (long)KVDIM * HW);
}

// round 11
// speedup vs baseline: 2.7949x; 1.9865x over previous
#include <cuda_runtime.h>
#include <cuda_bf16.h>
#include <math.h>
#include <stdint.h>

#define CDIM   192
#define KVDIM  384
#define HEADS  6
#define CPH    32
#define WIDTH  160
#define HW     25600          // 160*160
#define BATCH  8
#define NSPLIT 16

// ---------------- scratch (device globals; no allocation) ----------------
__device__ float g_q   [(size_t)BATCH * CDIM  * HW];   // q after 1x1
__device__ float g_kv  [(size_t)BATCH * KVDIM * HW];   // kv after 1x1
__device__ float g_qd  [(size_t)BATCH * CDIM  * HW];   // q after dw3x3
__device__ float g_kvd [(size_t)BATCH * KVDIM * HW];   // k|v after dw3x3
__device__ float g_S   [BATCH * HEADS * CPH * CPH];    // raw gram
__device__ float g_NQ  [BATCH * HEADS * CPH];          // sum q^2
__device__ float g_NK  [BATCH * HEADS * CPH];          // sum k^2
__device__ float g_A   [BATCH * HEADS * CPH * CPH];    // softmax(attn)
// pre-split bf16 weights (hi/lo) for tensor-core GEMMs
__device__ __nv_bfloat16 g_Wqh [CDIM  * CDIM];
__device__ __nv_bfloat16 g_Wql [CDIM  * CDIM];
__device__ __nv_bfloat16 g_Wkvh[KVDIM * CDIM];
__device__ __nv_bfloat16 g_Wkvl[KVDIM * CDIM];
__device__ __nv_bfloat16 g_Mh  [BATCH * CDIM * CDIM];  // W_out @ blockdiag(A), hi
__device__ __nv_bfloat16 g_Ml  [BATCH * CDIM * CDIM];  // lo

// ================= warp-MMA helpers (arch-agnostic PTX) =================
__device__ __forceinline__ uint32_t smem_u32(const void* p) {
    uint32_t a;
    asm("{ .reg .u64 t; cvta.to.shared.u64 t, %1; cvt.u32.u64 %0, t; }" : "=r"(a) : "l"(p));
    return a;
}
__device__ __forceinline__ void ldsm_x4(uint32_t (&r)[4], uint32_t addr) {
    asm volatile("ldmatrix.sync.aligned.m8n8.x4.shared.b16 {%0,%1,%2,%3}, [%4];"
        : "=r"(r[0]), "=r"(r[1]), "=r"(r[2]), "=r"(r[3]) : "r"(addr));
}
__device__ __forceinline__ void ldsm_x4_t(uint32_t (&r)[4], uint32_t addr) {
    asm volatile("ldmatrix.sync.aligned.m8n8.x4.trans.shared.b16 {%0,%1,%2,%3}, [%4];"
        : "=r"(r[0]), "=r"(r[1]), "=r"(r[2]), "=r"(r[3]) : "r"(addr));
}
__device__ __forceinline__ void mma_bf16(float (&d)[4], const uint32_t (&a)[4],
                                         uint32_t b0, uint32_t b1) {
    asm volatile("mma.sync.aligned.m16n8k16.row.col.f32.bf16.bf16.f32 "
        "{%0,%1,%2,%3}, {%4,%5,%6,%7}, {%8,%9}, {%0,%1,%2,%3};"
        : "+f"(d[0]), "+f"(d[1]), "+f"(d[2]), "+f"(d[3])
        : "r"(a[0]), "r"(a[1]), "r"(a[2]), "r"(a[3]), "r"(b0), "r"(b1));
}

// ============ tensor-core GEMM (mma.sync bf16, 3-term fp32 split) ============
// Y[b, o0+m, n0+n] = sum_k W[o0+m][k] * X[b][k][n0+n]
// BM=64 (cout m), BN=128 (spatial n), BK=32, 256 thr = 2x4 warps, warp = 32x32.
#define APAD 40     // 64 x 40 bf16 rows (80 B row: ldmatrix conflict-free)
#define BPAD 136    // 32 x 136 bf16 rows (272 B row: conflict-free)

__global__ __launch_bounds__(256) void gemm_mma(
    const __nv_bfloat16* __restrict__ Wh, const __nv_bfloat16* __restrict__ Wl,
    const float* __restrict__ X, float* __restrict__ Y,
    int O, long wBatch, long xBatch)
{
    __shared__ __align__(16) __nv_bfloat16 sA[2][64][APAD];   // [hi/lo][m][k]
    __shared__ __align__(16) __nv_bfloat16 sB[2][32][BPAD];   // [hi/lo][k][n]

    const int tid  = threadIdx.x;
    const int wid  = tid >> 5, lane = tid & 31;
    const int wm   = wid >> 2;          // 0..1  -> m offset *32
    const int wn   = wid & 3;           // 0..3  -> n offset *32
    const int n0   = blockIdx.x * 128;
    const int o0   = blockIdx.y * 64;
    const int b    = blockIdx.z;

    const __nv_bfloat16* Whb = Wh + (size_t)b * wBatch + (size_t)o0 * CDIM;
    const __nv_bfloat16* Wlb = Wl + (size_t)b * wBatch + (size_t)o0 * CDIM;
    const float* Xb = X + (size_t)b * xBatch + n0;

    // per-lane ldmatrix source coords
    const int aRow = (lane & 7) + ((lane >> 3) & 1) * 8;   // within 16
    const int aCol = ((lane >> 4) & 1) * 8;
    const int bRow = (lane & 7) + ((lane >> 3) & 1) * 8;   // k within 16
    const int bCol = ((lane >> 4) & 1) * 8;

    const uint32_t sA0 = smem_u32(&sA[0][0][0]);
    const uint32_t sA1 = smem_u32(&sA[1][0][0]);
    const uint32_t sB0 = smem_u32(&sB[0][0][0]);
    const uint32_t sB1 = smem_u32(&sB[1][0][0]);

    float acc[2][4][4] = {};   // [mt][nt][frag]

    for (int kb = 0; kb < 6; kb++) {
        const int k0 = kb * 32;
        // ---- stage A: W chunk [64 m x 32 k], hi and lo ----
        #pragma unroll
        for (int i = 0; i < 2; i++) {
            int f = tid + i * 256;             // 0..511 groups of 4 bf16
            int m = f >> 3, k4 = (f & 7) * 4;
            uint2 vh = *(const uint2*)(Whb + (size_t)m * CDIM + k0 + k4);
            uint2 vl = *(const uint2*)(Wlb + (size_t)m * CDIM + k0 + k4);
            *(uint2*)&sA[0][m][k4] = vh;
            *(uint2*)&sA[1][m][k4] = vl;
        }
        // ---- stage B: X chunk [32 k x 128 n] fp32 -> bf16 hi/lo ----
        #pragma unroll
        for (int i = 0; i < 4; i++) {
            int f = tid + i * 256;             // 0..1023 float4 groups
            int k = f >> 5, n4 = (f & 31) * 4;
            float4 v = *(const float4*)(Xb + (size_t)(k0 + k) * HW + n4);
            __nv_bfloat16 h0 = __float2bfloat16(v.x), h1 = __float2bfloat16(v.y);
            __nv_bfloat16 h2 = __float2bfloat16(v.z), h3 = __float2bfloat16(v.w);
            __nv_bfloat16 l0 = __float2bfloat16(v.x - __bfloat162float(h0));
            __nv_bfloat16 l1 = __float2bfloat16(v.y - __bfloat162float(h1));
            __nv_bfloat16 l2 = __float2bfloat16(v.z - __bfloat162float(h2));
            __nv_bfloat16 l3 = __float2bfloat16(v.w - __bfloat162float(h3));
            uint2 ph, pl;
            ph.x = (uint32_t)__bfloat16_as_ushort(h0) | ((uint32_t)__bfloat16_as_ushort(h1) << 16);
            ph.y = (uint32_t)__bfloat16_as_ushort(h2) | ((uint32_t)__bfloat16_as_ushort(h3) << 16);
            pl.x = (uint32_t)__bfloat16_as_ushort(l0) | ((uint32_t)__bfloat16_as_ushort(l1) << 16);
            pl.y = (uint32_t)__bfloat16_as_ushort(l2) | ((uint32_t)__bfloat16_as_ushort(l3) << 16);
            *(uint2*)&sB[0][k][n4] = ph;
            *(uint2*)&sB[1][k][n4] = pl;
        }
        __syncthreads();

        #pragma unroll
        for (int ks = 0; ks < 2; ks++) {
            uint32_t ah[2][4], al[2][4], bh[2][4], bl[2][4];
            #pragma unroll
            for (int mt = 0; mt < 2; mt++) {
                uint32_t off = (uint32_t)((wm * 32 + mt * 16 + aRow) * APAD
                                          + ks * 16 + aCol) * 2;
                ldsm_x4(ah[mt], sA0 + off);
                ldsm_x4(al[mt], sA1 + off);
            }
            #pragma unroll
            for (int np = 0; np < 2; np++) {
                uint32_t off = (uint32_t)((ks * 16 + bRow) * BPAD
                                          + wn * 32 + np * 16 + bCol) * 2;
                ldsm_x4_t(bh[np], sB0 + off);
                ldsm_x4_t(bl[np], sB1 + off);
            }
            #pragma unroll
            for (int mt = 0; mt < 2; mt++)
                #pragma unroll
                for (int np = 0; np < 2; np++)
                    #pragma unroll
                    for (int s = 0; s < 2; s++) {
                        int nt = np * 2 + s;
                        mma_bf16(acc[mt][nt], ah[mt], bh[np][s*2], bh[np][s*2+1]); // hi*hi
                        mma_bf16(acc[mt][nt], ah[mt], bl[np][s*2], bl[np][s*2+1]); // hi*lo
                        mma_bf16(acc[mt][nt], al[mt], bh[np][s*2], bh[np][s*2+1]); // lo*hi
                    }
        }
        __syncthreads();
    }

    // ---- epilogue: D m16n8 fragment -> float2 stores ----
    const int g = lane >> 2, cc = (lane & 3) * 2;
    #pragma unroll
    for (int mt = 0; mt < 2; mt++) {
        #pragma unroll
        for (int nt = 0; nt < 4; nt++) {
            int orow = o0 + wm * 32 + mt * 16 + g;
            int ncol = n0 + wn * 32 + nt * 8 + cc;
            float2 v0 = make_float2(acc[mt][nt][0], acc[mt][nt][1]);
            float2 v1 = make_float2(acc[mt][nt][2], acc[mt][nt][3]);
            *(float2*)&Y[((size_t)b * O + orow    ) * HW + ncol] = v0;
            *(float2*)&Y[((size_t)b * O + orow + 8) * HW + ncol] = v1;
        }
    }
}

// ---------------- split fp32 weights into bf16 hi/lo ----------------------
__global__ void split_w(const float* __restrict__ wq, const float* __restrict__ wkv) {
    int i = blockIdx.x * 256 + threadIdx.x;
    if (i < CDIM * CDIM) {
        float f = wq[i];
        __nv_bfloat16 h = __float2bfloat16(f);
        g_Wqh[i] = h;
        g_Wql[i] = __float2bfloat16(f - __bfloat162float(h));
    }
    if (i < KVDIM * CDIM) {
        float f = wkv[i];
        __nv_bfloat16 h = __float2bfloat16(f);
        g_Wkvh[i] = h;
        g_Wkvl[i] = __float2bfloat16(f - __bfloat162float(h));
    }
}

// ---------------- depthwise 3x3, pad 1 — row-strip smem version -----------
__global__ __launch_bounds__(160) void dwconv3x3_v2(
    const float* __restrict__ X, const float* __restrict__ Wd,
    float* __restrict__ Y, int C)
{
    __shared__ float s[10][WIDTH];
    const int b = blockIdx.z, ch = blockIdx.y;
    const int r0 = blockIdx.x * 8;
    const int w = threadIdx.x;                 // 0..159, fixed column
    const float* xp = X + ((size_t)b * C + ch) * HW;
    #pragma unroll
    for (int i = 0; i < 10; i++) {
        int r = r0 - 1 + i;
        s[i][w] = (r >= 0 && r < WIDTH) ? xp[r * WIDTH + w] : 0.f;
    }
    const float* wp = Wd + ch * 9;
    float c00 = wp[0], c01 = wp[1], c02 = wp[2];
    float c10 = wp[3], c11 = wp[4], c12 = wp[5];
    float c20 = wp[6], c21 = wp[7], c22 = wp[8];
    __syncthreads();
    const bool wl = (w > 0), wr = (w < WIDTH - 1);
    float* yp = Y + ((size_t)b * C + ch) * HW + r0 * WIDTH + w;
    #pragma unroll
    for (int r = 0; r < 8; r++) {
        float a0 = wl ? s[r][w-1] : 0.f, a1 = s[r][w],   a2 = wr ? s[r][w+1] : 0.f;
        float b0 = wl ? s[r+1][w-1] : 0.f, b1 = s[r+1][w], b2 = wr ? s[r+1][w+1] : 0.f;
        float d0 = wl ? s[r+2][w-1] : 0.f, d1 = s[r+2][w], d2 = wr ? s[r+2][w+1] : 0.f;
        float acc = c00*a0 + c01*a1 + c02*a2
                  + c10*b0 + c11*b1 + c12*b2
                  + c20*d0 + c21*d1 + c22*d2;
        yp[r * WIDTH] = acc;
    }
}

// ---------------- zero the gram accumulators -------------------------------
__global__ void zero_acc() {
    int i = blockIdx.x * 256 + threadIdx.x;
    const int nS = BATCH * HEADS * CPH * CPH;
    const int nN = BATCH * HEADS * CPH;
    if (i < nS) g_S[i] = 0.f;
    if (i < nN) { g_NQ[i] = 0.f; g_NK[i] = 0.f; }
}

// ---------------- Gram: S[b,h,c,d] = sum_n q[c,n] k[d,n]; plus sum q^2, k^2
__global__ __launch_bounds__(256) void gram(
    const float* __restrict__ Q, const float* __restrict__ K)
{
    __shared__ float qs[32][33];
    __shared__ float ks[32][33];
    const int b = blockIdx.z, hh = blockIdx.y, split = blockIdx.x;
    const int tid = threadIdx.x;
    const float* qb = Q + ((size_t)b * CDIM  + hh * CPH) * HW;
    const float* kb = K + ((size_t)b * KVDIM + hh * CPH) * HW;
    const int chunk = HW / NSPLIT;
    const int nbeg = split * chunk;
    const int ty = tid >> 4, tx = tid & 15;
    const int lc = tid >> 3;
    const int lj = (tid & 7) * 4;

    float acc00 = 0, acc01 = 0, acc10 = 0, acc11 = 0;
    float aq0 = 0, aq1 = 0, ak0 = 0, ak1 = 0;

    for (int n0 = nbeg; n0 < nbeg + chunk; n0 += 32) {
        float4 vq = *(const float4*)&qb[(size_t)lc * HW + n0 + lj];
        float4 vk = *(const float4*)&kb[(size_t)lc * HW + n0 + lj];
        qs[lc][lj] = vq.x; qs[lc][lj+1] = vq.y; qs[lc][lj+2] = vq.z; qs[lc][lj+3] = vq.w;
        ks[lc][lj] = vk.x; ks[lc][lj+1] = vk.y; ks[lc][lj+2] = vk.z; ks[lc][lj+3] = vk.w;
        __syncthreads();
        #pragma unroll
        for (int t = 0; t < 32; t++) {
            float q0 = qs[ty*2][t],  q1 = qs[ty*2+1][t];
            float k0 = ks[tx*2][t],  k1 = ks[tx*2+1][t];
            acc00 += q0*k0; acc01 += q0*k1; acc10 += q1*k0; acc11 += q1*k1;
            if (tx == 0) { aq0 += q0*q0; aq1 += q1*q1; }
            if (ty == 0) { ak0 += k0*k0; ak1 += k1*k1; }
        }
        __syncthreads();
    }
    float* Sb = g_S + (size_t)(b * HEADS + hh) * CPH * CPH;
    atomicAdd(&Sb[(ty*2    ) * CPH + tx*2    ], acc00);
    atomicAdd(&Sb[(ty*2    ) * CPH + tx*2 + 1], acc01);
    atomicAdd(&Sb[(ty*2 + 1) * CPH + tx*2    ], acc10);
    atomicAdd(&Sb[(ty*2 + 1) * CPH + tx*2 + 1], acc11);
    if (tx == 0) {
        atomicAdd(&g_NQ[(b * HEADS + hh) * CPH + ty*2    ], aq0);
        atomicAdd(&g_NQ[(b * HEADS + hh) * CPH + ty*2 + 1], aq1);
    }
    if (ty == 0) {
        atomicAdd(&g_NK[(b * HEADS + hh) * CPH + tx*2    ], ak0);
        atomicAdd(&g_NK[(b * HEADS + hh) * CPH + tx*2 + 1], ak1);
    }
}

// ---------------- softmax over d with L2-norm scaling + temperature --------
__global__ void softmax_attn(const float* __restrict__ temp) {
    const int bh = blockIdx.x;
    const int h  = bh % HEADS;
    const int d  = threadIdx.x;
    const float t = temp[h];
    float nk = fmaxf(sqrtf(g_NK[bh * CPH + d]), 1e-12f);
    for (int c = 0; c < CPH; c++) {
        float nq = fmaxf(sqrtf(g_NQ[bh * CPH + c]), 1e-12f);
        float v = g_S[bh * CPH * CPH + c * CPH + d] / (nq * nk) * t;
        float m = v;
        #pragma unroll
        for (int o = 16; o; o >>= 1) m = fmaxf(m, __shfl_xor_sync(~0u, m, o));
        float e = __expf(v - m);
        float s = e;
        #pragma unroll
        for (int o = 16; o; o >>= 1) s += __shfl_xor_sync(~0u, s, o);
        g_A[bh * CPH * CPH + c * CPH + d] = e / s;
    }
}

// ---------------- fold: M[b,o,g] = sum_c Wout[o, h*32+c] * A[b,h,c,d] ------
// emits bf16 hi/lo directly for the tensor-core final GEMM
__global__ __launch_bounds__(256) void foldM(const float* __restrict__ Wout) {
    const int b = blockIdx.y;
    const int idx = blockIdx.x * 256 + threadIdx.x;     // 0..192*192-1
    const int o = idx / CDIM, g = idx % CDIM;
    const int h = g / CPH, d = g % CPH;
    const float* Ab = g_A + (size_t)(b * HEADS + h) * CPH * CPH;
    float acc = 0.f;
    #pragma unroll
    for (int c = 0; c < CPH; c++)
        acc += Wout[o * CDIM + h * CPH + c] * Ab[c * CPH + d];
    __nv_bfloat16 hh = __float2bfloat16(acc);
    g_Mh[(size_t)b * CDIM * CDIM + idx] = hh;
    g_Ml[(size_t)b * CDIM * CDIM + idx] = __float2bfloat16(acc - __bfloat162float(hh));
}

// ---------------- launch --------------------------------------------------
extern "C" void kernel_launch(void* const* d_in, const int* in_sizes, int n_in,
                              void* d_out, int out_size)
{
    const float* x_q   = (const float*)d_in[0];
    const float* x_kv  = (const float*)d_in[1];
    const float* w_q   = (const float*)d_in[2];
    const float* w_kv  = (const float*)d_in[3];
    const float* w_qdw = (const float*)d_in[4];
    const float* w_kvdw= (const float*)d_in[5];
    const float* w_out = (const float*)d_in[6];
    const float* temp  = (const float*)d_in[7];
    float* out = (float*)d_out;

    float *bq, *bkv, *bqd, *bkvd;
    __nv_bfloat16 *wqh, *wql, *wkvh, *wkvl, *mh, *ml;
    cudaGetSymbolAddress((void**)&bq,   g_q);
    cudaGetSymbolAddress((void**)&bkv,  g_kv);
    cudaGetSymbolAddress((void**)&bqd,  g_qd);
    cudaGetSymbolAddress((void**)&bkvd, g_kvd);
    cudaGetSymbolAddress((void**)&wqh,  g_Wqh);
    cudaGetSymbolAddress((void**)&wql,  g_Wql);
    cudaGetSymbolAddress((void**)&wkvh, g_Wkvh);
    cudaGetSymbolAddress((void**)&wkvl, g_Wkvl);
    cudaGetSymbolAddress((void**)&mh,   g_Mh);
    cudaGetSymbolAddress((void**)&ml,   g_Ml);

    // 0) split weights to bf16 hi/lo
    split_w<<<(KVDIM * CDIM + 255) / 256, 256>>>(w_q, w_kv);
    // 1) q = W_q @ x_q   (tensor cores, mma.sync)
    gemm_mma<<<dim3(HW/128, CDIM/64, BATCH), 256>>>(
        wqh, wql, x_q, bq, CDIM, 0, (long)CDIM * HW);
    // 2) kv = W_kv @ x_kv (384 outputs)
    gemm_mma<<<dim3(HW/128, KVDIM/64, BATCH), 256>>>(
        wkvh, wkvl, x_kv, bkv, KVDIM, 0, (long)CDIM * HW);
    // 3) depthwise 3x3
    dwconv3x3_v2<<<dim3(WIDTH/8, CDIM,  BATCH), WIDTH>>>(bq,  w_qdw,  bqd,  CDIM);
    dwconv3x3_v2<<<dim3(WIDTH/8, KVDIM, BATCH), WIDTH>>>(bkv, w_kvdw, bkvd, KVDIM);
    // 4) zero gram accumulators
    zero_acc<<<(BATCH*HEADS*CPH*CPH + 255)/256, 256>>>();
    // 5) gram + norms (k = first DIM channels of kvd)
    gram<<<dim3(NSPLIT, HEADS, BATCH), 256>>>(bqd, bkvd);
    // 6) softmax with normalization + temperature
    softmax_attn<<<BATCH * HEADS, 32>>>(temp);
    // 7) fold W_out with attention -> bf16 hi/lo M
    foldM<<<dim3(CDIM*CDIM/256, BATCH), 256>>>(w_out);
    // 8) out = M_b @ v   (tensor cores; v = second DIM channels of kvd)
    gemm_mma<<<dim3(HW/128, CDIM/64, BATCH), 256>>>(
        mh, ml, bkvd + (size_t)CDIM * HW, out, CDIM,
        (long)CDIM * CDIM, (long)KVDIM * HW);
}